// round 8
// baseline (speedup 1.0000x reference)
#include <cuda_runtime.h>
#include <cstdint>

// Problem dims (fixed for this problem instance)
#define B_DIM 32
#define T_DIM 2048
#define I_DIM 256            // K
#define H_DIM 512
#define M_DIM (B_DIM * T_DIM)   // 65536

#define ALPHA_MIN_F 0.8187307530779818f   // exp(-1/5)
#define ALPHA_MAX_F 0.9607894391523232f   // exp(-1/25)

// Scratch: pre-scaled projection  g_wx[m,h] = (1-alpha_h) * (x @ W^T)[m,h]
__device__ float g_wx[(size_t)M_DIM * H_DIM];

// ---- packed f32x2 helpers -------------------------------------------------
__device__ __forceinline__ uint64_t pack2(float lo, float hi) {
    uint64_t r;
    asm("mov.b64 %0, {%1, %2};" : "=l"(r) : "f"(lo), "f"(hi));
    return r;
}
__device__ __forceinline__ void unpack2(uint64_t v, float& lo, float& hi) {
    asm("mov.b64 {%0, %1}, %2;" : "=f"(lo), "=f"(hi) : "l"(v));
}
__device__ __forceinline__ uint64_t ffma2(uint64_t a, uint64_t b, uint64_t c) {
    uint64_t d;
    asm("fma.rn.f32x2 %0, %1, %2, %3;" : "=l"(d) : "l"(a), "l"(b), "l"(c));
    return d;
}

// ===========================================================================
// Pack-free FFMA2 GEMM: wx[m,h] = sum_k x[m,k] * W[h,k]  ("NT")
// BM=128, BN=128, BK=16, 256 threads, 8x8 outputs/thread held as 4 M-pairs
// x 8 N-cols of packed f32x2 accumulators.
//   a-operand {a_m, a_m+1}: adjacent in As -> direct LDS.128 (2 pairs)
//   b-operand {b_n, b_n}:   B stored DUPLICATED in smem -> direct LDS.128
// Inner loop: 32 FFMA2 + 6 LDS.128 per k per thread, ZERO pack movs.
// Double-buffered (2 stages), one __syncthreads per stage.
// Per-output accumulation: single FMA per k, k ascending -> wx bitwise
// identical to rounds 2-4 (rel_err 0.0 preserved).
// ===========================================================================
#define BK 16
#define NSTAGE (I_DIM / BK)          // 16
#define A_STRIDE 128                 // words per k-row in As
#define B_STRIDE 256                 // words per k-row in Bd (duplicated)

__global__ __launch_bounds__(256, 2) void lif_gemm_kernel(
    const float* __restrict__ X,
    const float* __restrict__ Wm,
    const float* __restrict__ alpha_in)
{
    __shared__ __align__(16) float As[2][BK][A_STRIDE];   // 2 x 8 KB
    __shared__ __align__(16) float Bd[2][BK][B_STRIDE];   // 2 x 16 KB

    const int tid = threadIdx.x;
    const int tx  = tid & 15;   // N direction
    const int ty  = tid >> 4;   // M direction

    const int m0 = (blockIdx.x >> 2) * 128;
    const int h0 = (blockIdx.x & 3) * 128;

    // GMEM staging: thread -> row = tid>>1 (0..127), k-half = (tid&1)*8
    const int lrow = tid >> 1;
    const int lkh  = (tid & 1) * 8;
    const float* Ap = X  + (size_t)(m0 + lrow) * I_DIM + lkh;
    const float* Bp = Wm + (size_t)(h0 + lrow) * I_DIM + lkh;

    uint64_t acc2[4][8];
    #pragma unroll
    for (int p = 0; p < 4; p++)
        #pragma unroll
        for (int j = 0; j < 8; j++)
            acc2[p][j] = 0ull;

    // ---- staging store helpers (per 8-k half-row) ----
    auto stage_store = [&](int buf, float4 va, float4 vb) {
        // A: transposed scalar stores (k-major)
        As[buf][lkh + 0][lrow] = va.x;
        As[buf][lkh + 1][lrow] = va.y;
        As[buf][lkh + 2][lrow] = va.z;
        As[buf][lkh + 3][lrow] = va.w;
        // B: duplicated pair stores (STS.64 of {v,v})
        *(uint64_t*)&Bd[buf][lkh + 0][2 * lrow] = pack2(vb.x, vb.x);
        *(uint64_t*)&Bd[buf][lkh + 1][2 * lrow] = pack2(vb.y, vb.y);
        *(uint64_t*)&Bd[buf][lkh + 2][2 * lrow] = pack2(vb.z, vb.z);
        *(uint64_t*)&Bd[buf][lkh + 3][2 * lrow] = pack2(vb.w, vb.w);
    };

    // --- prologue: stage 0 -> smem buf0; stage 1 -> regs ---
    {
        float4 a0 = *(const float4*)(Ap);
        float4 a1 = *(const float4*)(Ap + 4);
        float4 b0 = *(const float4*)(Bp);
        float4 b1 = *(const float4*)(Bp + 4);
        stage_store(0, a0, b0);
        // second half of the 8 k-values
        As[0][lkh + 4][lrow] = a1.x;
        As[0][lkh + 5][lrow] = a1.y;
        As[0][lkh + 6][lrow] = a1.z;
        As[0][lkh + 7][lrow] = a1.w;
        *(uint64_t*)&Bd[0][lkh + 4][2 * lrow] = pack2(b1.x, b1.x);
        *(uint64_t*)&Bd[0][lkh + 5][2 * lrow] = pack2(b1.y, b1.y);
        *(uint64_t*)&Bd[0][lkh + 6][2 * lrow] = pack2(b1.z, b1.z);
        *(uint64_t*)&Bd[0][lkh + 7][2 * lrow] = pack2(b1.w, b1.w);
    }
    float4 na0 = *(const float4*)(Ap + BK);
    float4 na1 = *(const float4*)(Ap + BK + 4);
    float4 nb0 = *(const float4*)(Bp + BK);
    float4 nb1 = *(const float4*)(Bp + BK + 4);
    __syncthreads();

    #pragma unroll 1
    for (int s = 0; s < NSTAGE; s++) {
        // 1) STS stage s+1 into the other buffer
        if (s + 1 < NSTAGE) {
            const int nb = (s + 1) & 1;
            stage_store(nb, na0, nb0);
            As[nb][lkh + 4][lrow] = na1.x;
            As[nb][lkh + 5][lrow] = na1.y;
            As[nb][lkh + 6][lrow] = na1.z;
            As[nb][lkh + 7][lrow] = na1.w;
            *(uint64_t*)&Bd[nb][lkh + 4][2 * lrow] = pack2(nb1.x, nb1.x);
            *(uint64_t*)&Bd[nb][lkh + 5][2 * lrow] = pack2(nb1.y, nb1.y);
            *(uint64_t*)&Bd[nb][lkh + 6][2 * lrow] = pack2(nb1.z, nb1.z);
            *(uint64_t*)&Bd[nb][lkh + 7][2 * lrow] = pack2(nb1.w, nb1.w);
        }
        // 2) LDG stage s+2
        if (s + 2 < NSTAGE) {
            const float* An = Ap + (s + 2) * BK;
            const float* Bn = Bp + (s + 2) * BK;
            na0 = *(const float4*)(An);
            na1 = *(const float4*)(An + 4);
            nb0 = *(const float4*)(Bn);
            nb1 = *(const float4*)(Bn + 4);
        }

        // 3) FFMA2 over stage s (pack-free inner loop)
        const int buf = s & 1;
        #pragma unroll
        for (int k = 0; k < BK; k++) {
            // a-pairs: rows {ty*4..+3} and {64+ty*4..+3} -> 2 x LDS.128
            ulonglong2 la0 = *(const ulonglong2*)&As[buf][k][ty * 4];
            ulonglong2 la1 = *(const ulonglong2*)&As[buf][k][64 + ty * 4];
            // b-splats: dup'd cols -> 4 x LDS.128, each = 2 splat-pairs
            ulonglong2 lb0 = *(const ulonglong2*)&Bd[buf][k][tx * 8];
            ulonglong2 lb1 = *(const ulonglong2*)&Bd[buf][k][tx * 8 + 4];
            ulonglong2 lb2 = *(const ulonglong2*)&Bd[buf][k][128 + tx * 8];
            ulonglong2 lb3 = *(const ulonglong2*)&Bd[buf][k][128 + tx * 8 + 4];

            uint64_t ap[4] = {la0.x, la0.y, la1.x, la1.y};
            uint64_t bs[8] = {lb0.x, lb0.y, lb1.x, lb1.y,
                              lb2.x, lb2.y, lb3.x, lb3.y};
            #pragma unroll
            for (int p = 0; p < 4; p++)
                #pragma unroll
                for (int j = 0; j < 8; j++)
                    acc2[p][j] = ffma2(ap[p], bs[j], acc2[p][j]);
        }
        __syncthreads();
    }

    // Epilogue: scale by bc[h] = 1 - clamp(alpha[h]), store
    float bc[8];
    #pragma unroll
    for (int j = 0; j < 8; j++) {
        int col = h0 + ((j < 4) ? (tx * 4 + j) : (64 + tx * 4 + (j - 4)));
        float a = alpha_in[col];
        a = fminf(fmaxf(a, ALPHA_MIN_F), ALPHA_MAX_F);
        bc[j] = 1.0f - a;
    }

    #pragma unroll
    for (int i = 0; i < 8; i++) {
        const int p   = (i < 4) ? (i >> 1) : (2 + ((i - 4) >> 1));
        const int sel = i & 1;
        const int row = m0 + ((i < 4) ? (ty * 4 + i) : (64 + ty * 4 + (i - 4)));
        float v[8];
        #pragma unroll
        for (int j = 0; j < 8; j++) {
            float lo, hi;
            unpack2(acc2[p][j], lo, hi);
            v[j] = (sel ? hi : lo) * bc[j];
        }
        float* dst = &g_wx[(size_t)row * H_DIM + h0];
        *(float4*)(dst + tx * 4)      = make_float4(v[0], v[1], v[2], v[3]);
        *(float4*)(dst + 64 + tx * 4) = make_float4(v[4], v[5], v[6], v[7]);
    }
}

// ===========================================================================
// Scan (unchanged): one thread per (b,h) chain, distance-3 prefetch,
// predicate-form recurrence. At its structural latency-BW cap (~3 TB/s).
// ===========================================================================
__global__ __launch_bounds__(64) void lif_scan_kernel(
    const float* __restrict__ alpha_in,
    const float* __restrict__ u0,
    const float* __restrict__ s0,
    float* __restrict__ out)
{
    const int b = blockIdx.x >> 3;
    const int h = (blockIdx.x & 7) * 64 + threadIdx.x;

    float a = alpha_in[h];
    a = fminf(fmaxf(a, ALPHA_MIN_F), ALPHA_MAX_F);

    float u = u0[b * H_DIM + h];
    float s = s0[b * H_DIM + h];

    const float* __restrict__ wx = g_wx + (size_t)b * T_DIM * H_DIM + h;
    float* __restrict__ o = out + (size_t)b * T_DIM * H_DIM + h;

    constexpr int U = 16;
    constexpr int NCH = T_DIM / U;
    float buf[4][U];

    #pragma unroll
    for (int c0 = 0; c0 < 3; c0++) {
        const float* p = wx + (size_t)c0 * U * H_DIM;
        #pragma unroll
        for (int i = 0; i < U; i++)
            buf[c0][i] = p[(size_t)i * H_DIM];
    }

    {
        const float* p = wx + (size_t)3 * U * H_DIM;
        #pragma unroll
        for (int i = 0; i < U; i++)
            buf[3][i] = p[(size_t)i * H_DIM];

        #pragma unroll
        for (int i = 0; i < U; i++) {
            u = a * (u - s) + buf[0][i];            // buf already = bc*wx
            s = (u > 1.0f) ? 1.0f : 0.0f;
            o[(size_t)i * H_DIM] = s;
        }
    }
    bool pr = (s != 0.0f);

    #pragma unroll 4
    for (int c = 1; c < NCH; c++) {
        if (c + 3 < NCH) {
            const float* p = wx + (size_t)(c + 3) * U * H_DIM;
            #pragma unroll
            for (int i = 0; i < U; i++)
                buf[(c + 3) & 3][i] = p[(size_t)i * H_DIM];
        }
        float* po = o + (size_t)c * U * H_DIM;
        #pragma unroll
        for (int i = 0; i < U; i++) {
            float w  = buf[c & 3][i];
            float d  = u - 1.0f;
            float um = pr ? d : u;
            u  = fmaf(a, um, w);
            pr = (u > 1.0f);
            po[(size_t)i * H_DIM] = pr ? 1.0f : 0.0f;
        }
    }
}

// ---------------------------------------------------------------------------
// Launch
// ---------------------------------------------------------------------------
extern "C" void kernel_launch(void* const* d_in, const int* in_sizes, int n_in,
                              void* d_out, int out_size)
{
    const float* x     = (const float*)d_in[0];  // [B, T, I]
    const float* W     = (const float*)d_in[1];  // [H, I]
    const float* alpha = (const float*)d_in[2];  // [H]
    const float* u0    = (const float*)d_in[3];  // [B, H]
    const float* s0    = (const float*)d_in[4];  // [B, H]
    float* out = (float*)d_out;                  // [B, T, H]

    (void)in_sizes; (void)n_in; (void)out_size;

    // GEMM: 512 m-tiles x 4 h-tiles = 2048 CTAs of 256 threads
    lif_gemm_kernel<<<2048, 256>>>(x, W, alpha);

    // Scan: 32 batches x 8 h-chunks = 256 CTAs of 64 threads
    lif_scan_kernel<<<B_DIM * 8, 64>>>(alpha, u0, s0, out);
}

// round 9
// speedup vs baseline: 1.4538x; 1.4538x over previous
#include <cuda_runtime.h>
#include <cstdint>

// Problem dims (fixed for this problem instance)
#define B_DIM 32
#define T_DIM 2048
#define I_DIM 256            // K
#define H_DIM 512
#define M_DIM (B_DIM * T_DIM)   // 65536

#define ALPHA_MIN_F 0.8187307530779818f   // exp(-1/5)
#define ALPHA_MAX_F 0.9607894391523232f   // exp(-1/25)

// Scratch: pre-scaled projection  g_wx[m,h] = (1-alpha_h) * (x @ W^T)[m,h]
__device__ float g_wx[(size_t)M_DIM * H_DIM];

// ---- packed f32x2 helpers -------------------------------------------------
__device__ __forceinline__ uint64_t pack2(float lo, float hi) {
    uint64_t r;
    asm("mov.b64 %0, {%1, %2};" : "=l"(r) : "f"(lo), "f"(hi));
    return r;
}
__device__ __forceinline__ void unpack2(uint64_t v, float& lo, float& hi) {
    asm("mov.b64 {%0, %1}, %2;" : "=f"(lo), "=f"(hi) : "l"(v));
}
__device__ __forceinline__ uint64_t ffma2(uint64_t a, uint64_t b, uint64_t c) {
    uint64_t d;
    asm("fma.rn.f32x2 %0, %1, %2, %3;" : "=l"(d) : "l"(a), "l"(b), "l"(c));
    return d;
}

// ===========================================================================
// Pack-free FFMA2 GEMM, round-4 pairing: wx[m,h] = sum_k x[m,k] * W[h,k]
// BM=128, BN=128, BK=16, 256 threads, 8x8 outputs/thread as 8 rows x 4
// N-pair f32x2 accumulators {out[m][2j], out[m][2j+1]} (same as round 4).
//   b-operand {b_2j, b_2j+1}: adjacent in plain k-major Bs -> direct
//     ulonglong2 LDS.128 (round-4-proven conflict-free: tx*16B stride).
//   a-operand {a_m, a_m}:     A stored DUPLICATED in smem; address depends
//     only on ty -> 2 distinct addrs/warp -> pure broadcast, conflict-free.
// Inner loop: 32 FFMA2 + 6 LDS.128 per k, ZERO pack movs (vs round 4's 12).
// Double-buffered (2 stages), one __syncthreads per stage.
// Per-output math identical to rounds 2-4 -> wx bitwise identical.
// ===========================================================================
#define BK 16
#define NSTAGE (I_DIM / BK)          // 16
#define AD_STRIDE 256                // words per k-row in Ad (duplicated)
#define B_STRIDE 128                 // words per k-row in Bs

__global__ __launch_bounds__(256, 2) void lif_gemm_kernel(
    const float* __restrict__ X,
    const float* __restrict__ Wm,
    const float* __restrict__ alpha_in)
{
    __shared__ __align__(16) float Ad[2][BK][AD_STRIDE];  // 32 KB (dup'd A)
    __shared__ __align__(16) float Bs[2][BK][B_STRIDE];   // 16 KB

    const int tid = threadIdx.x;
    const int tx  = tid & 15;   // N direction
    const int ty  = tid >> 4;   // M direction

    const int m0 = (blockIdx.x >> 2) * 128;
    const int h0 = (blockIdx.x & 3) * 128;

    // GMEM staging: thread -> row = tid>>1 (0..127), k-half = (tid&1)*8
    const int lrow = tid >> 1;
    const int lkh  = (tid & 1) * 8;
    const float* Ap = X  + (size_t)(m0 + lrow) * I_DIM + lkh;
    const float* Bp = Wm + (size_t)(h0 + lrow) * I_DIM + lkh;

    uint64_t acc2[8][4];
    #pragma unroll
    for (int i = 0; i < 8; i++)
        #pragma unroll
        for (int j = 0; j < 4; j++)
            acc2[i][j] = 0ull;

    // ---- staging store: A duplicated ({v,v} STS.64), B plain scalar ----
    auto stage_store = [&](int buf, float4 a0, float4 a1, float4 b0, float4 b1) {
        *(uint64_t*)&Ad[buf][lkh + 0][2 * lrow] = pack2(a0.x, a0.x);
        *(uint64_t*)&Ad[buf][lkh + 1][2 * lrow] = pack2(a0.y, a0.y);
        *(uint64_t*)&Ad[buf][lkh + 2][2 * lrow] = pack2(a0.z, a0.z);
        *(uint64_t*)&Ad[buf][lkh + 3][2 * lrow] = pack2(a0.w, a0.w);
        *(uint64_t*)&Ad[buf][lkh + 4][2 * lrow] = pack2(a1.x, a1.x);
        *(uint64_t*)&Ad[buf][lkh + 5][2 * lrow] = pack2(a1.y, a1.y);
        *(uint64_t*)&Ad[buf][lkh + 6][2 * lrow] = pack2(a1.z, a1.z);
        *(uint64_t*)&Ad[buf][lkh + 7][2 * lrow] = pack2(a1.w, a1.w);
        Bs[buf][lkh + 0][lrow] = b0.x;
        Bs[buf][lkh + 1][lrow] = b0.y;
        Bs[buf][lkh + 2][lrow] = b0.z;
        Bs[buf][lkh + 3][lrow] = b0.w;
        Bs[buf][lkh + 4][lrow] = b1.x;
        Bs[buf][lkh + 5][lrow] = b1.y;
        Bs[buf][lkh + 6][lrow] = b1.z;
        Bs[buf][lkh + 7][lrow] = b1.w;
    };

    // --- prologue: stage 0 -> smem buf0; stage 1 -> regs ---
    {
        float4 a0 = *(const float4*)(Ap);
        float4 a1 = *(const float4*)(Ap + 4);
        float4 b0 = *(const float4*)(Bp);
        float4 b1 = *(const float4*)(Bp + 4);
        stage_store(0, a0, a1, b0, b1);
    }
    float4 na0 = *(const float4*)(Ap + BK);
    float4 na1 = *(const float4*)(Ap + BK + 4);
    float4 nb0 = *(const float4*)(Bp + BK);
    float4 nb1 = *(const float4*)(Bp + BK + 4);
    __syncthreads();

    #pragma unroll 1
    for (int s = 0; s < NSTAGE; s++) {
        // 1) STS stage s+1 into the other buffer
        if (s + 1 < NSTAGE)
            stage_store((s + 1) & 1, na0, na1, nb0, nb1);
        // 2) LDG stage s+2
        if (s + 2 < NSTAGE) {
            const float* An = Ap + (s + 2) * BK;
            const float* Bn = Bp + (s + 2) * BK;
            na0 = *(const float4*)(An);
            na1 = *(const float4*)(An + 4);
            nb0 = *(const float4*)(Bn);
            nb1 = *(const float4*)(Bn + 4);
        }

        // 3) FFMA2 over stage s (pack-free inner loop)
        const int buf = s & 1;
        #pragma unroll
        for (int k = 0; k < BK; k++) {
            // A splat-pairs: rows ty*4..+3 and 64+ty*4..+3 from dup'd Ad.
            // Addresses depend only on ty -> warp broadcast, conflict-free.
            ulonglong2 sa0 = *(const ulonglong2*)&Ad[buf][k][ty * 8];
            ulonglong2 sa1 = *(const ulonglong2*)&Ad[buf][k][ty * 8 + 4];
            ulonglong2 sa2 = *(const ulonglong2*)&Ad[buf][k][128 + ty * 8];
            ulonglong2 sa3 = *(const ulonglong2*)&Ad[buf][k][128 + ty * 8 + 4];
            // B col-pairs: {b_2j, b_2j+1} adjacent -> direct 64-bit operands
            ulonglong2 pb0 = *(const ulonglong2*)&Bs[buf][k][tx * 4];
            ulonglong2 pb1 = *(const ulonglong2*)&Bs[buf][k][64 + tx * 4];

            uint64_t ap[8] = {sa0.x, sa0.y, sa1.x, sa1.y,
                              sa2.x, sa2.y, sa3.x, sa3.y};
            uint64_t bp[4] = {pb0.x, pb0.y, pb1.x, pb1.y};
            #pragma unroll
            for (int i = 0; i < 8; i++)
                #pragma unroll
                for (int j = 0; j < 4; j++)
                    acc2[i][j] = ffma2(ap[i], bp[j], acc2[i][j]);
        }
        __syncthreads();
    }

    // Epilogue: scale by bc[h] = 1 - clamp(alpha[h]), store (round-4 layout)
    float bc[8];
    #pragma unroll
    for (int jj = 0; jj < 8; jj++) {
        int col = h0 + ((jj < 4) ? (tx * 4 + jj) : (64 + tx * 4 + (jj - 4)));
        float a = alpha_in[col];
        a = fminf(fmaxf(a, ALPHA_MIN_F), ALPHA_MAX_F);
        bc[jj] = 1.0f - a;
    }

    #pragma unroll
    for (int i = 0; i < 8; i++) {
        int row = m0 + ((i < 4) ? (ty * 4 + i) : (64 + ty * 4 + (i - 4)));
        float c0, c1, c2, c3, c4, c5, c6, c7;
        unpack2(acc2[i][0], c0, c1);
        unpack2(acc2[i][1], c2, c3);
        unpack2(acc2[i][2], c4, c5);
        unpack2(acc2[i][3], c6, c7);
        float* dst = &g_wx[(size_t)row * H_DIM + h0];
        *(float4*)(dst + tx * 4) =
            make_float4(c0 * bc[0], c1 * bc[1], c2 * bc[2], c3 * bc[3]);
        *(float4*)(dst + 64 + tx * 4) =
            make_float4(c4 * bc[4], c5 * bc[5], c6 * bc[6], c7 * bc[7]);
    }
}

// ===========================================================================
// Scan (unchanged): one thread per (b,h) chain, distance-3 prefetch,
// predicate-form recurrence. At its structural latency-BW cap (~3 TB/s).
// ===========================================================================
__global__ __launch_bounds__(64) void lif_scan_kernel(
    const float* __restrict__ alpha_in,
    const float* __restrict__ u0,
    const float* __restrict__ s0,
    float* __restrict__ out)
{
    const int b = blockIdx.x >> 3;
    const int h = (blockIdx.x & 7) * 64 + threadIdx.x;

    float a = alpha_in[h];
    a = fminf(fmaxf(a, ALPHA_MIN_F), ALPHA_MAX_F);

    float u = u0[b * H_DIM + h];
    float s = s0[b * H_DIM + h];

    const float* __restrict__ wx = g_wx + (size_t)b * T_DIM * H_DIM + h;
    float* __restrict__ o = out + (size_t)b * T_DIM * H_DIM + h;

    constexpr int U = 16;
    constexpr int NCH = T_DIM / U;
    float buf[4][U];

    #pragma unroll
    for (int c0 = 0; c0 < 3; c0++) {
        const float* p = wx + (size_t)c0 * U * H_DIM;
        #pragma unroll
        for (int i = 0; i < U; i++)
            buf[c0][i] = p[(size_t)i * H_DIM];
    }

    {
        const float* p = wx + (size_t)3 * U * H_DIM;
        #pragma unroll
        for (int i = 0; i < U; i++)
            buf[3][i] = p[(size_t)i * H_DIM];

        #pragma unroll
        for (int i = 0; i < U; i++) {
            u = a * (u - s) + buf[0][i];            // buf already = bc*wx
            s = (u > 1.0f) ? 1.0f : 0.0f;
            o[(size_t)i * H_DIM] = s;
        }
    }
    bool pr = (s != 0.0f);

    #pragma unroll 4
    for (int c = 1; c < NCH; c++) {
        if (c + 3 < NCH) {
            const float* p = wx + (size_t)(c + 3) * U * H_DIM;
            #pragma unroll
            for (int i = 0; i < U; i++)
                buf[(c + 3) & 3][i] = p[(size_t)i * H_DIM];
        }
        float* po = o + (size_t)c * U * H_DIM;
        #pragma unroll
        for (int i = 0; i < U; i++) {
            float w  = buf[c & 3][i];
            float d  = u - 1.0f;
            float um = pr ? d : u;
            u  = fmaf(a, um, w);
            pr = (u > 1.0f);
            po[(size_t)i * H_DIM] = pr ? 1.0f : 0.0f;
        }
    }
}

// ---------------------------------------------------------------------------
// Launch
// ---------------------------------------------------------------------------
extern "C" void kernel_launch(void* const* d_in, const int* in_sizes, int n_in,
                              void* d_out, int out_size)
{
    const float* x     = (const float*)d_in[0];  // [B, T, I]
    const float* W     = (const float*)d_in[1];  // [H, I]
    const float* alpha = (const float*)d_in[2];  // [H]
    const float* u0    = (const float*)d_in[3];  // [B, H]
    const float* s0    = (const float*)d_in[4];  // [B, H]
    float* out = (float*)d_out;                  // [B, T, H]

    (void)in_sizes; (void)n_in; (void)out_size;

    // GEMM: 512 m-tiles x 4 h-tiles = 2048 CTAs of 256 threads
    lif_gemm_kernel<<<2048, 256>>>(x, W, alpha);

    // Scan: 32 batches x 8 h-chunks = 256 CTAs of 64 threads
    lif_scan_kernel<<<B_DIM * 8, 64>>>(alpha, u0, s0, out);
}

// round 10
// speedup vs baseline: 1.5652x; 1.0766x over previous
#include <cuda_runtime.h>
#include <cstdint>

// Problem dims (fixed for this problem instance)
#define B_DIM 32
#define T_DIM 2048
#define I_DIM 256            // K
#define H_DIM 512
#define M_DIM (B_DIM * T_DIM)   // 65536

#define ALPHA_MIN_F 0.8187307530779818f   // exp(-1/5)
#define ALPHA_MAX_F 0.9607894391523232f   // exp(-1/25)

// Scratch: pre-scaled projection  g_wx[m,h] = (1-alpha_h) * (x @ W^T)[m,h]
__device__ float g_wx[(size_t)M_DIM * H_DIM];

// ---- packed f32x2 helpers -------------------------------------------------
__device__ __forceinline__ uint64_t pack2(float lo, float hi) {
    uint64_t r;
    asm("mov.b64 %0, {%1, %2};" : "=l"(r) : "f"(lo), "f"(hi));
    return r;
}
__device__ __forceinline__ void unpack2(uint64_t v, float& lo, float& hi) {
    asm("mov.b64 {%0, %1}, %2;" : "=f"(lo), "=f"(hi) : "l"(v));
}
__device__ __forceinline__ uint64_t ffma2(uint64_t a, uint64_t b, uint64_t c) {
    uint64_t d;
    asm("fma.rn.f32x2 %0, %1, %2, %3;" : "=l"(d) : "l"(a), "l"(b), "l"(c));
    return d;
}

// ===========================================================================
// FFMA2 GEMM (round-4 proven core): wx[m,h] = sum_k x[m,k] * W[h,k]  ("NT")
// BM=128, BN=128, BK=16, 256 threads, 8 rows x 4 N-pair f32x2 accs/thread.
//   b-operands: {b_2j, b_2j+1} read DIRECTLY as ulonglong2 from k-major Bs
//               (no packs; tx*16B stride = conflict-free).
//   a-operands: splat pairs via pack2(a,a) - 8 packs per k (round-4 proven).
// Single-__syncthreads double-buffer schedule (round-7 pattern).
// Per-output accumulation: single FMA per k, k ascending -> wx bitwise
// identical to rounds 2-4 (rel_err 0.0 preserved).
// Takes a grid-offset arg so the launch can be split into 3 sub-launches
// (per-replay launch count 2 -> 4, putting ncu's "-s 5 -c 1" on a GEMM).
// ===========================================================================
#define BK 16
#define NSTAGE (I_DIM / BK)          // 16

__global__ __launch_bounds__(256, 2) void lif_gemm_kernel(
    const float* __restrict__ X,
    const float* __restrict__ Wm,
    const float* __restrict__ alpha_in,
    int bid0)
{
    __shared__ __align__(16) float As[2][BK][128];   // 16 KB
    __shared__ __align__(16) float Bs[2][BK][128];   // 16 KB

    const int tid = threadIdx.x;
    const int tx  = tid & 15;   // N direction
    const int ty  = tid >> 4;   // M direction

    const int bid = bid0 + blockIdx.x;
    const int m0 = (bid >> 2) * 128;
    const int h0 = (bid & 3) * 128;

    // GMEM staging: thread -> row = tid>>1 (0..127), k-half = (tid&1)*8
    const int lrow = tid >> 1;
    const int lkh  = (tid & 1) * 8;
    const float* Ap = X  + (size_t)(m0 + lrow) * I_DIM + lkh;
    const float* Bp = Wm + (size_t)(h0 + lrow) * I_DIM + lkh;

    uint64_t acc2[8][4];
    #pragma unroll
    for (int i = 0; i < 8; i++)
        #pragma unroll
        for (int j = 0; j < 4; j++)
            acc2[i][j] = 0ull;

    // ---- staging store (scalar transposed stores, k-major) ----
    auto stage_store = [&](int buf, float4 a0, float4 a1, float4 b0, float4 b1) {
        As[buf][lkh + 0][lrow] = a0.x;
        As[buf][lkh + 1][lrow] = a0.y;
        As[buf][lkh + 2][lrow] = a0.z;
        As[buf][lkh + 3][lrow] = a0.w;
        As[buf][lkh + 4][lrow] = a1.x;
        As[buf][lkh + 5][lrow] = a1.y;
        As[buf][lkh + 6][lrow] = a1.z;
        As[buf][lkh + 7][lrow] = a1.w;
        Bs[buf][lkh + 0][lrow] = b0.x;
        Bs[buf][lkh + 1][lrow] = b0.y;
        Bs[buf][lkh + 2][lrow] = b0.z;
        Bs[buf][lkh + 3][lrow] = b0.w;
        Bs[buf][lkh + 4][lrow] = b1.x;
        Bs[buf][lkh + 5][lrow] = b1.y;
        Bs[buf][lkh + 6][lrow] = b1.z;
        Bs[buf][lkh + 7][lrow] = b1.w;
    };

    // --- prologue: stage 0 -> smem buf0; stage 1 -> regs ---
    {
        float4 a0 = *(const float4*)(Ap);
        float4 a1 = *(const float4*)(Ap + 4);
        float4 b0 = *(const float4*)(Bp);
        float4 b1 = *(const float4*)(Bp + 4);
        stage_store(0, a0, a1, b0, b1);
    }
    float4 na0 = *(const float4*)(Ap + BK);
    float4 na1 = *(const float4*)(Ap + BK + 4);
    float4 nb0 = *(const float4*)(Bp + BK);
    float4 nb1 = *(const float4*)(Bp + BK + 4);
    __syncthreads();

    #pragma unroll 1
    for (int s = 0; s < NSTAGE; s++) {
        // 1) STS stage s+1 into the other buffer
        if (s + 1 < NSTAGE)
            stage_store((s + 1) & 1, na0, na1, nb0, nb1);
        // 2) LDG stage s+2
        if (s + 2 < NSTAGE) {
            const float* An = Ap + (s + 2) * BK;
            const float* Bn = Bp + (s + 2) * BK;
            na0 = *(const float4*)(An);
            na1 = *(const float4*)(An + 4);
            nb0 = *(const float4*)(Bn);
            nb1 = *(const float4*)(Bn + 4);
        }

        // 3) FFMA2 over stage s (round-4 proven inner loop)
        const int buf = s & 1;
        #pragma unroll
        for (int k = 0; k < BK; k++) {
            // a scalars: rows ty*4..+3 and 64+ty*4..+3 -> 2 x LDS.128
            float4 ra0 = *(const float4*)(&As[buf][k][ty * 4]);
            float4 ra1 = *(const float4*)(&As[buf][k][64 + ty * 4]);
            // b pairs: direct 64-bit operands, no packs
            ulonglong2 pb0 = *(const ulonglong2*)(&Bs[buf][k][tx * 4]);
            ulonglong2 pb1 = *(const ulonglong2*)(&Bs[buf][k][64 + tx * 4]);

            uint64_t bp[4] = {pb0.x, pb0.y, pb1.x, pb1.y};
            float ra[8] = {ra0.x, ra0.y, ra0.z, ra0.w,
                           ra1.x, ra1.y, ra1.z, ra1.w};
            #pragma unroll
            for (int i = 0; i < 8; i++) {
                uint64_t ad = pack2(ra[i], ra[i]);
                #pragma unroll
                for (int j = 0; j < 4; j++)
                    acc2[i][j] = ffma2(ad, bp[j], acc2[i][j]);
            }
        }
        __syncthreads();
    }

    // Epilogue: scale by bc[h] = 1 - clamp(alpha[h]), store (round-4 layout)
    float bc[8];
    #pragma unroll
    for (int jj = 0; jj < 8; jj++) {
        int col = h0 + ((jj < 4) ? (tx * 4 + jj) : (64 + tx * 4 + (jj - 4)));
        float a = alpha_in[col];
        a = fminf(fmaxf(a, ALPHA_MIN_F), ALPHA_MAX_F);
        bc[jj] = 1.0f - a;
    }

    #pragma unroll
    for (int i = 0; i < 8; i++) {
        int row = m0 + ((i < 4) ? (ty * 4 + i) : (64 + ty * 4 + (i - 4)));
        float c0, c1, c2, c3, c4, c5, c6, c7;
        unpack2(acc2[i][0], c0, c1);
        unpack2(acc2[i][1], c2, c3);
        unpack2(acc2[i][2], c4, c5);
        unpack2(acc2[i][3], c6, c7);
        float* dst = &g_wx[(size_t)row * H_DIM + h0];
        *(float4*)(dst + tx * 4) =
            make_float4(c0 * bc[0], c1 * bc[1], c2 * bc[2], c3 * bc[3]);
        *(float4*)(dst + 64 + tx * 4) =
            make_float4(c4 * bc[4], c5 * bc[5], c6 * bc[6], c7 * bc[7]);
    }
}

// ===========================================================================
// Scan (unchanged): one thread per (b,h) chain, distance-3 prefetch,
// predicate-form recurrence. At its structural latency-BW cap (~3 TB/s).
// ===========================================================================
__global__ __launch_bounds__(64) void lif_scan_kernel(
    const float* __restrict__ alpha_in,
    const float* __restrict__ u0,
    const float* __restrict__ s0,
    float* __restrict__ out)
{
    const int b = blockIdx.x >> 3;
    const int h = (blockIdx.x & 7) * 64 + threadIdx.x;

    float a = alpha_in[h];
    a = fminf(fmaxf(a, ALPHA_MIN_F), ALPHA_MAX_F);

    float u = u0[b * H_DIM + h];
    float s = s0[b * H_DIM + h];

    const float* __restrict__ wx = g_wx + (size_t)b * T_DIM * H_DIM + h;
    float* __restrict__ o = out + (size_t)b * T_DIM * H_DIM + h;

    constexpr int U = 16;
    constexpr int NCH = T_DIM / U;
    float buf[4][U];

    #pragma unroll
    for (int c0 = 0; c0 < 3; c0++) {
        const float* p = wx + (size_t)c0 * U * H_DIM;
        #pragma unroll
        for (int i = 0; i < U; i++)
            buf[c0][i] = p[(size_t)i * H_DIM];
    }

    {
        const float* p = wx + (size_t)3 * U * H_DIM;
        #pragma unroll
        for (int i = 0; i < U; i++)
            buf[3][i] = p[(size_t)i * H_DIM];

        #pragma unroll
        for (int i = 0; i < U; i++) {
            u = a * (u - s) + buf[0][i];            // buf already = bc*wx
            s = (u > 1.0f) ? 1.0f : 0.0f;
            o[(size_t)i * H_DIM] = s;
        }
    }
    bool pr = (s != 0.0f);

    #pragma unroll 4
    for (int c = 1; c < NCH; c++) {
        if (c + 3 < NCH) {
            const float* p = wx + (size_t)(c + 3) * U * H_DIM;
            #pragma unroll
            for (int i = 0; i < U; i++)
                buf[(c + 3) & 3][i] = p[(size_t)i * H_DIM];
        }
        float* po = o + (size_t)c * U * H_DIM;
        #pragma unroll
        for (int i = 0; i < U; i++) {
            float w  = buf[c & 3][i];
            float d  = u - 1.0f;
            float um = pr ? d : u;
            u  = fmaf(a, um, w);
            pr = (u > 1.0f);
            po[(size_t)i * H_DIM] = pr ? 1.0f : 0.0f;
        }
    }
}

// ---------------------------------------------------------------------------
// Launch. GEMM split into 3 sub-launches (same total work) so the ncu
// capture window (-s 5 -c 1; 4 launches per replay) lands on a GEMM launch
// instead of always profiling the scan.
// ---------------------------------------------------------------------------
extern "C" void kernel_launch(void* const* d_in, const int* in_sizes, int n_in,
                              void* d_out, int out_size)
{
    const float* x     = (const float*)d_in[0];  // [B, T, I]
    const float* W     = (const float*)d_in[1];  // [H, I]
    const float* alpha = (const float*)d_in[2];  // [H]
    const float* u0    = (const float*)d_in[3];  // [B, H]
    const float* s0    = (const float*)d_in[4];  // [B, H]
    float* out = (float*)d_out;                  // [B, T, H]

    (void)in_sizes; (void)n_in; (void)out_size;

    // GEMM: 2048 tiles total, split 688 + 688 + 672
    lif_gemm_kernel<<<688, 256>>>(x, W, alpha, 0);
    lif_gemm_kernel<<<688, 256>>>(x, W, alpha, 688);
    lif_gemm_kernel<<<672, 256>>>(x, W, alpha, 1376);

    // Scan: 32 batches x 8 h-chunks = 256 CTAs of 64 threads
    lif_scan_kernel<<<B_DIM * 8, 64>>>(alpha, u0, s0, out);
}

// round 11
// speedup vs baseline: 1.6250x; 1.0382x over previous
#include <cuda_runtime.h>
#include <cstdint>

// Problem dims (fixed for this problem instance)
#define B_DIM 32
#define T_DIM 2048
#define I_DIM 256            // K
#define H_DIM 512
#define M_DIM (B_DIM * T_DIM)   // 65536

#define ALPHA_MIN_F 0.8187307530779818f   // exp(-1/5)
#define ALPHA_MAX_F 0.9607894391523232f   // exp(-1/25)

// Scratch: pre-scaled projection  g_wx[m,h] = (1-alpha_h) * (x @ W^T)[m,h]
__device__ float g_wx[(size_t)M_DIM * H_DIM];

// ---- packed f32x2 helpers -------------------------------------------------
__device__ __forceinline__ uint64_t pack2(float lo, float hi) {
    uint64_t r;
    asm("mov.b64 %0, {%1, %2};" : "=l"(r) : "f"(lo), "f"(hi));
    return r;
}
__device__ __forceinline__ void unpack2(uint64_t v, float& lo, float& hi) {
    asm("mov.b64 {%0, %1}, %2;" : "=f"(lo), "=f"(hi) : "l"(v));
}
__device__ __forceinline__ uint64_t ffma2(uint64_t a, uint64_t b, uint64_t c) {
    uint64_t d;
    asm("fma.rn.f32x2 %0, %1, %2, %3;" : "=l"(d) : "l"(a), "l"(b), "l"(c));
    return d;
}

// ===========================================================================
// FFMA2 GEMM, widened thread tile: wx[m,h] = sum_k x[m,k] * W[h,k]  ("NT")
// CTA tile 128(m) x 256(n), BK=16, 256 threads, 8x16 outputs/thread held as
// 8 rows x 8 N-pair f32x2 accumulators (128 acc regs -> 1 CTA/SM).
// Per k: 64 FFMA2 + 6 LDS.128 + 8 a-splat packs = 78 slots / 64 FFMA2
// (vs round-4's 52/32) -> predicted ~255-285us for the GEMM.
//   b-operands: {b_2j, b_2j+1} direct ulonglong2 from k-major Bs
//               (tx*16B stride: phase-conflict-free, round-4-proven).
//   a-operands: splat pack2(a,a); As addresses depend only on ty (broadcast).
// Single-__syncthreads double-buffer schedule; LDG prefetch distance 2.
// Per-output accumulation: single FMA per k, k ascending -> wx bitwise
// identical to rounds 2-4 (rel_err 0.0 preserved).
// ===========================================================================
#define BK 16
#define NSTAGE (I_DIM / BK)          // 16

__global__ __launch_bounds__(256, 1) void lif_gemm_kernel(
    const float* __restrict__ X,
    const float* __restrict__ Wm,
    const float* __restrict__ alpha_in)
{
    __shared__ __align__(16) float As[2][BK][128];   // 16 KB
    __shared__ __align__(16) float Bs[2][BK][256];   // 32 KB

    const int tid = threadIdx.x;
    const int tx  = tid & 15;   // N direction (16 groups x 16 cols)
    const int ty  = tid >> 4;   // M direction (16 groups x 8 rows)

    const int m0 = (int)(blockIdx.x >> 1) * 128;
    const int h0 = (int)(blockIdx.x & 1) * 256;

    // GMEM staging mappings
    //   A: row = tid>>1 (0..127), k-half = (tid&1)*8  -> 2 float4 / stage
    //   B: row = tid (0..255), all 16 k               -> 4 float4 / stage
    const int lrow = tid >> 1;
    const int lkh  = (tid & 1) * 8;
    const float* Ap = X  + (size_t)(m0 + lrow) * I_DIM + lkh;
    const float* Bp = Wm + (size_t)(h0 + tid) * I_DIM;

    uint64_t acc2[8][8];
    #pragma unroll
    for (int i = 0; i < 8; i++)
        #pragma unroll
        for (int j = 0; j < 8; j++)
            acc2[i][j] = 0ull;

    // ---- staging store (scalar transposed stores, k-major) ----
    auto stage_store = [&](int buf, float4 a0, float4 a1,
                           float4 b0, float4 b1, float4 b2, float4 b3) {
        As[buf][lkh + 0][lrow] = a0.x;
        As[buf][lkh + 1][lrow] = a0.y;
        As[buf][lkh + 2][lrow] = a0.z;
        As[buf][lkh + 3][lrow] = a0.w;
        As[buf][lkh + 4][lrow] = a1.x;
        As[buf][lkh + 5][lrow] = a1.y;
        As[buf][lkh + 6][lrow] = a1.z;
        As[buf][lkh + 7][lrow] = a1.w;
        Bs[buf][ 0][tid] = b0.x;  Bs[buf][ 1][tid] = b0.y;
        Bs[buf][ 2][tid] = b0.z;  Bs[buf][ 3][tid] = b0.w;
        Bs[buf][ 4][tid] = b1.x;  Bs[buf][ 5][tid] = b1.y;
        Bs[buf][ 6][tid] = b1.z;  Bs[buf][ 7][tid] = b1.w;
        Bs[buf][ 8][tid] = b2.x;  Bs[buf][ 9][tid] = b2.y;
        Bs[buf][10][tid] = b2.z;  Bs[buf][11][tid] = b2.w;
        Bs[buf][12][tid] = b3.x;  Bs[buf][13][tid] = b3.y;
        Bs[buf][14][tid] = b3.z;  Bs[buf][15][tid] = b3.w;
    };

    // --- prologue: stage 0 -> smem buf0; stage 1 -> regs ---
    {
        float4 a0 = *(const float4*)(Ap);
        float4 a1 = *(const float4*)(Ap + 4);
        float4 b0 = *(const float4*)(Bp);
        float4 b1 = *(const float4*)(Bp + 4);
        float4 b2 = *(const float4*)(Bp + 8);
        float4 b3 = *(const float4*)(Bp + 12);
        stage_store(0, a0, a1, b0, b1, b2, b3);
    }
    float4 na0 = *(const float4*)(Ap + BK);
    float4 na1 = *(const float4*)(Ap + BK + 4);
    float4 nb0 = *(const float4*)(Bp + BK);
    float4 nb1 = *(const float4*)(Bp + BK + 4);
    float4 nb2 = *(const float4*)(Bp + BK + 8);
    float4 nb3 = *(const float4*)(Bp + BK + 12);
    __syncthreads();

    #pragma unroll 1
    for (int s = 0; s < NSTAGE; s++) {
        // 1) STS stage s+1 into the other buffer
        if (s + 1 < NSTAGE)
            stage_store((s + 1) & 1, na0, na1, nb0, nb1, nb2, nb3);
        // 2) LDG stage s+2
        if (s + 2 < NSTAGE) {
            const float* An = Ap + (s + 2) * BK;
            const float* Bn = Bp + (s + 2) * BK;
            na0 = *(const float4*)(An);
            na1 = *(const float4*)(An + 4);
            nb0 = *(const float4*)(Bn);
            nb1 = *(const float4*)(Bn + 4);
            nb2 = *(const float4*)(Bn + 8);
            nb3 = *(const float4*)(Bn + 12);
        }

        // 3) FFMA2 over stage s
        const int buf = s & 1;
        #pragma unroll
        for (int k = 0; k < BK; k++) {
            // a scalars: rows ty*4..+3 and 64+ty*4..+3 -> 2 x LDS.128
            // (addresses depend only on ty -> warp broadcast)
            float4 ra0 = *(const float4*)(&As[buf][k][ty * 4]);
            float4 ra1 = *(const float4*)(&As[buf][k][64 + ty * 4]);
            // b pairs: 4 quads, direct 64-bit operands (no packs)
            ulonglong2 pb0 = *(const ulonglong2*)(&Bs[buf][k][tx * 4]);
            ulonglong2 pb1 = *(const ulonglong2*)(&Bs[buf][k][64 + tx * 4]);
            ulonglong2 pb2 = *(const ulonglong2*)(&Bs[buf][k][128 + tx * 4]);
            ulonglong2 pb3 = *(const ulonglong2*)(&Bs[buf][k][192 + tx * 4]);

            uint64_t bp[8] = {pb0.x, pb0.y, pb1.x, pb1.y,
                              pb2.x, pb2.y, pb3.x, pb3.y};
            float ra[8] = {ra0.x, ra0.y, ra0.z, ra0.w,
                           ra1.x, ra1.y, ra1.z, ra1.w};
            #pragma unroll
            for (int i = 0; i < 8; i++) {
                uint64_t ad = pack2(ra[i], ra[i]);
                #pragma unroll
                for (int j = 0; j < 8; j++)
                    acc2[i][j] = ffma2(ad, bp[j], acc2[i][j]);
            }
        }
        __syncthreads();
    }

    // Epilogue: scale by bc[h] = 1 - clamp(alpha[h]), store
    // Column map: acc2[i][2q+p] covers cols q*64 + tx*4 + p*2 + {0,1}
    float bc[16];
    #pragma unroll
    for (int q = 0; q < 4; q++)
        #pragma unroll
        for (int jj = 0; jj < 4; jj++) {
            int col = h0 + q * 64 + tx * 4 + jj;
            float a = alpha_in[col];
            a = fminf(fmaxf(a, ALPHA_MIN_F), ALPHA_MAX_F);
            bc[q * 4 + jj] = 1.0f - a;
        }

    #pragma unroll
    for (int i = 0; i < 8; i++) {
        int row = m0 + ((i < 4) ? (ty * 4 + i) : (64 + ty * 4 + (i - 4)));
        float* dst = &g_wx[(size_t)row * H_DIM + h0];
        #pragma unroll
        for (int q = 0; q < 4; q++) {
            float c0, c1, c2, c3;
            unpack2(acc2[i][2 * q + 0], c0, c1);
            unpack2(acc2[i][2 * q + 1], c2, c3);
            *(float4*)(dst + q * 64 + tx * 4) =
                make_float4(c0 * bc[q * 4 + 0], c1 * bc[q * 4 + 1],
                            c2 * bc[q * 4 + 2], c3 * bc[q * 4 + 3]);
        }
    }
}

// ===========================================================================
// Scan (unchanged): one thread per (b,h) chain, distance-3 prefetch,
// predicate-form recurrence. At its structural latency-BW cap (~3 TB/s).
// ===========================================================================
__global__ __launch_bounds__(64) void lif_scan_kernel(
    const float* __restrict__ alpha_in,
    const float* __restrict__ u0,
    const float* __restrict__ s0,
    float* __restrict__ out)
{
    const int b = blockIdx.x >> 3;
    const int h = (blockIdx.x & 7) * 64 + threadIdx.x;

    float a = alpha_in[h];
    a = fminf(fmaxf(a, ALPHA_MIN_F), ALPHA_MAX_F);

    float u = u0[b * H_DIM + h];
    float s = s0[b * H_DIM + h];

    const float* __restrict__ wx = g_wx + (size_t)b * T_DIM * H_DIM + h;
    float* __restrict__ o = out + (size_t)b * T_DIM * H_DIM + h;

    constexpr int U = 16;
    constexpr int NCH = T_DIM / U;
    float buf[4][U];

    #pragma unroll
    for (int c0 = 0; c0 < 3; c0++) {
        const float* p = wx + (size_t)c0 * U * H_DIM;
        #pragma unroll
        for (int i = 0; i < U; i++)
            buf[c0][i] = p[(size_t)i * H_DIM];
    }

    {
        const float* p = wx + (size_t)3 * U * H_DIM;
        #pragma unroll
        for (int i = 0; i < U; i++)
            buf[3][i] = p[(size_t)i * H_DIM];

        #pragma unroll
        for (int i = 0; i < U; i++) {
            u = a * (u - s) + buf[0][i];            // buf already = bc*wx
            s = (u > 1.0f) ? 1.0f : 0.0f;
            o[(size_t)i * H_DIM] = s;
        }
    }
    bool pr = (s != 0.0f);

    #pragma unroll 4
    for (int c = 1; c < NCH; c++) {
        if (c + 3 < NCH) {
            const float* p = wx + (size_t)(c + 3) * U * H_DIM;
            #pragma unroll
            for (int i = 0; i < U; i++)
                buf[(c + 3) & 3][i] = p[(size_t)i * H_DIM];
        }
        float* po = o + (size_t)c * U * H_DIM;
        #pragma unroll
        for (int i = 0; i < U; i++) {
            float w  = buf[c & 3][i];
            float d  = u - 1.0f;
            float um = pr ? d : u;
            u  = fmaf(a, um, w);
            pr = (u > 1.0f);
            po[(size_t)i * H_DIM] = pr ? 1.0f : 0.0f;
        }
    }
}

// ---------------------------------------------------------------------------
// Launch
// ---------------------------------------------------------------------------
extern "C" void kernel_launch(void* const* d_in, const int* in_sizes, int n_in,
                              void* d_out, int out_size)
{
    const float* x     = (const float*)d_in[0];  // [B, T, I]
    const float* W     = (const float*)d_in[1];  // [H, I]
    const float* alpha = (const float*)d_in[2];  // [H]
    const float* u0    = (const float*)d_in[3];  // [B, H]
    const float* s0    = (const float*)d_in[4];  // [B, H]
    float* out = (float*)d_out;                  // [B, T, H]

    (void)in_sizes; (void)n_in; (void)out_size;

    // GEMM: 512 m-tiles x 2 n-tiles = 1024 CTAs of 256 threads (single launch)
    lif_gemm_kernel<<<1024, 256>>>(x, W, alpha);

    // Scan: 32 batches x 8 h-chunks = 256 CTAs of 64 threads
    lif_scan_kernel<<<B_DIM * 8, 64>>>(alpha, u0, s0, out);
}

// round 12
// speedup vs baseline: 1.7223x; 1.0599x over previous
#include <cuda_runtime.h>
#include <cstdint>

// Problem dims (fixed for this problem instance)
#define B_DIM 32
#define T_DIM 2048
#define I_DIM 256            // K
#define H_DIM 512
#define M_DIM (B_DIM * T_DIM)   // 65536

#define ALPHA_MIN_F 0.8187307530779818f   // exp(-1/5)
#define ALPHA_MAX_F 0.9607894391523232f   // exp(-1/25)

// Scratch: pre-scaled projection  g_wx[m,h] = (1-alpha_h) * (x @ W^T)[m,h]
__device__ float g_wx[(size_t)M_DIM * H_DIM];

// ---- packed f32x2 helpers -------------------------------------------------
__device__ __forceinline__ uint64_t pack2(float lo, float hi) {
    uint64_t r;
    asm("mov.b64 %0, {%1, %2};" : "=l"(r) : "f"(lo), "f"(hi));
    return r;
}
__device__ __forceinline__ void unpack2(uint64_t v, float& lo, float& hi) {
    asm("mov.b64 {%0, %1}, %2;" : "=f"(lo), "=f"(hi) : "l"(v));
}
__device__ __forceinline__ uint64_t ffma2(uint64_t a, uint64_t b, uint64_t c) {
    uint64_t d;
    asm("fma.rn.f32x2 %0, %1, %2, %3;" : "=l"(d) : "l"(a), "l"(b), "l"(c));
    return d;
}

// ===========================================================================
// GEMM: EXACT round-4 kernel (proven 319us, bitwise-stable wx).
// wx[m, h] = sum_k x[m, k] * W[h, k]; epilogue scales by bc[h].
// BM=128, BN=128, BK=16; 256 threads; 8x8 outputs/thread as 8x4 packed
// f32x2 accumulators. Double-buffered smem + LDG prefetch.
// ===========================================================================
__global__ __launch_bounds__(256, 2) void lif_gemm_kernel(
    const float* __restrict__ A,
    const float* __restrict__ W,
    const float* __restrict__ alpha_in)
{
    constexpr int BM = 128, BN = 128, BK = 16;
    __shared__ __align__(16) float As[2][BK][BM];
    __shared__ __align__(16) float Bs[2][BK][BN];

    const int tid = threadIdx.x;
    const int tx  = tid & 15;   // N direction
    const int ty  = tid >> 4;   // M direction

    const int m0 = blockIdx.y * BM;
    const int n0 = blockIdx.x * BN;

    const int lrow = tid >> 1;        // 0..127
    const int lk   = (tid & 1) * 8;   // 0 or 8

    const float* Aptr = A + (size_t)(m0 + lrow) * I_DIM + lk;
    const float* Wptr = W + (size_t)(n0 + lrow) * I_DIM + lk;

    uint64_t acc2[8][4];
    #pragma unroll
    for (int i = 0; i < 8; i++)
        #pragma unroll
        for (int j = 0; j < 4; j++)
            acc2[i][j] = 0ull;

    // Preload tile 0
    float4 a0 = *(const float4*)(Aptr);
    float4 a1 = *(const float4*)(Aptr + 4);
    float4 b0 = *(const float4*)(Wptr);
    float4 b1 = *(const float4*)(Wptr + 4);

    int buf = 0;
    As[0][lk + 0][lrow] = a0.x; As[0][lk + 1][lrow] = a0.y;
    As[0][lk + 2][lrow] = a0.z; As[0][lk + 3][lrow] = a0.w;
    As[0][lk + 4][lrow] = a1.x; As[0][lk + 5][lrow] = a1.y;
    As[0][lk + 6][lrow] = a1.z; As[0][lk + 7][lrow] = a1.w;
    Bs[0][lk + 0][lrow] = b0.x; Bs[0][lk + 1][lrow] = b0.y;
    Bs[0][lk + 2][lrow] = b0.z; Bs[0][lk + 3][lrow] = b0.w;
    Bs[0][lk + 4][lrow] = b1.x; Bs[0][lk + 5][lrow] = b1.y;
    Bs[0][lk + 6][lrow] = b1.z; Bs[0][lk + 7][lrow] = b1.w;
    __syncthreads();

    constexpr int KO_N = I_DIM / BK;   // 16
    #pragma unroll 1
    for (int ko = 0; ko < KO_N; ko++) {
        if (ko < KO_N - 1) {
            const float* Ap = Aptr + (ko + 1) * BK;
            const float* Wp = Wptr + (ko + 1) * BK;
            a0 = *(const float4*)(Ap);
            a1 = *(const float4*)(Ap + 4);
            b0 = *(const float4*)(Wp);
            b1 = *(const float4*)(Wp + 4);
        }

        #pragma unroll
        for (int k = 0; k < BK; k++) {
            float4 ra0 = *(const float4*)(&As[buf][k][ty * 4]);
            float4 ra1 = *(const float4*)(&As[buf][k][64 + ty * 4]);
            float4 rb0 = *(const float4*)(&Bs[buf][k][tx * 4]);
            float4 rb1 = *(const float4*)(&Bs[buf][k][64 + tx * 4]);

            uint64_t bp[4];
            bp[0] = pack2(rb0.x, rb0.y);
            bp[1] = pack2(rb0.z, rb0.w);
            bp[2] = pack2(rb1.x, rb1.y);
            bp[3] = pack2(rb1.z, rb1.w);

            float ra[8] = {ra0.x, ra0.y, ra0.z, ra0.w,
                           ra1.x, ra1.y, ra1.z, ra1.w};
            #pragma unroll
            for (int i = 0; i < 8; i++) {
                uint64_t ad = pack2(ra[i], ra[i]);
                #pragma unroll
                for (int j = 0; j < 4; j++)
                    acc2[i][j] = ffma2(ad, bp[j], acc2[i][j]);
            }
        }

        if (ko < KO_N - 1) {
            int nb = buf ^ 1;
            As[nb][lk + 0][lrow] = a0.x; As[nb][lk + 1][lrow] = a0.y;
            As[nb][lk + 2][lrow] = a0.z; As[nb][lk + 3][lrow] = a0.w;
            As[nb][lk + 4][lrow] = a1.x; As[nb][lk + 5][lrow] = a1.y;
            As[nb][lk + 6][lrow] = a1.z; As[nb][lk + 7][lrow] = a1.w;
            Bs[nb][lk + 0][lrow] = b0.x; Bs[nb][lk + 1][lrow] = b0.y;
            Bs[nb][lk + 2][lrow] = b0.z; Bs[nb][lk + 3][lrow] = b0.w;
            Bs[nb][lk + 4][lrow] = b1.x; Bs[nb][lk + 5][lrow] = b1.y;
            Bs[nb][lk + 6][lrow] = b1.z; Bs[nb][lk + 7][lrow] = b1.w;
            __syncthreads();
            buf = nb;
        }
    }

    // Epilogue: scale by bc[h] = 1 - clamp(alpha[h]), then store
    float bcv[8];
    #pragma unroll
    for (int jj = 0; jj < 8; jj++) {
        int col = n0 + ((jj < 4) ? (tx * 4 + jj) : (64 + tx * 4 + (jj - 4)));
        float a = alpha_in[col];
        a = fminf(fmaxf(a, ALPHA_MIN_F), ALPHA_MAX_F);
        bcv[jj] = 1.0f - a;
    }

    #pragma unroll
    for (int i = 0; i < 8; i++) {
        int row = m0 + ((i < 4) ? (ty * 4 + i) : (64 + ty * 4 + (i - 4)));
        float c0, c1, c2, c3, c4, c5, c6, c7;
        unpack2(acc2[i][0], c0, c1);
        unpack2(acc2[i][1], c2, c3);
        unpack2(acc2[i][2], c4, c5);
        unpack2(acc2[i][3], c6, c7);
        float* dst = &g_wx[(size_t)row * H_DIM + n0];
        *(float4*)(dst + tx * 4) =
            make_float4(c0 * bcv[0], c1 * bcv[1], c2 * bcv[2], c3 * bcv[3]);
        *(float4*)(dst + 64 + tx * 4) =
            make_float4(c4 * bcv[4], c5 * bcv[5], c6 * bcv[6], c7 * bcv[7]);
    }
}

// ===========================================================================
// Scan: U widened 16 -> 32 (NBUF=4, distance-3). Lead time per chunk
// doubles to ~1800 cyc > DRAM latency -> loads fully hidden.
// Chunk 0 peeled in general float-s form (s0 non-binary); steady state uses
// the bitwise-identical predicate form. All buffer indices static after
// unroll -> 128-reg buffer stays in registers.
// ===========================================================================
__global__ __launch_bounds__(64) void lif_scan_kernel(
    const float* __restrict__ alpha_in,
    const float* __restrict__ u0,
    const float* __restrict__ s0,
    float* __restrict__ out)
{
    const int b = blockIdx.x >> 3;
    const int h = (blockIdx.x & 7) * 64 + threadIdx.x;

    float a = alpha_in[h];
    a = fminf(fmaxf(a, ALPHA_MIN_F), ALPHA_MAX_F);

    float u = u0[b * H_DIM + h];
    float s = s0[b * H_DIM + h];

    const float* __restrict__ wx = g_wx + (size_t)b * T_DIM * H_DIM + h;
    float* __restrict__ o = out + (size_t)b * T_DIM * H_DIM + h;

    constexpr int U = 32;
    constexpr int NCH = T_DIM / U;   // 64
    float buf[4][U];                 // 128 regs, all indices static

    // Prologue: issue loads for chunks 0, 1, 2
    #pragma unroll
    for (int c0 = 0; c0 < 3; c0++) {
        const float* p = wx + (size_t)c0 * U * H_DIM;
        #pragma unroll
        for (int i = 0; i < U; i++)
            buf[c0][i] = p[(size_t)i * H_DIM];
    }

    // ---- chunk 0: general float-s form (s0 is arbitrary float) ----
    {
        const float* p = wx + (size_t)3 * U * H_DIM;
        #pragma unroll
        for (int i = 0; i < U; i++)
            buf[3][i] = p[(size_t)i * H_DIM];

        #pragma unroll
        for (int i = 0; i < U; i++) {
            u = a * (u - s) + buf[0][i];            // buf already = bc*wx
            s = (u > 1.0f) ? 1.0f : 0.0f;
            o[(size_t)i * H_DIM] = s;
        }
    }
    bool pr = (s != 0.0f);

    // ---- chunks 1..63: predicate form, distance-3 prefetch ----
    #pragma unroll 4
    for (int c = 1; c < NCH; c++) {
        if (c + 3 < NCH) {
            const float* p = wx + (size_t)(c + 3) * U * H_DIM;
            #pragma unroll
            for (int i = 0; i < U; i++)
                buf[(c + 3) & 3][i] = p[(size_t)i * H_DIM];
        }
        float* po = o + (size_t)c * U * H_DIM;
        #pragma unroll
        for (int i = 0; i < U; i++) {
            float w  = buf[c & 3][i];
            float d  = u - 1.0f;
            float um = pr ? d : u;
            u  = fmaf(a, um, w);
            pr = (u > 1.0f);
            po[(size_t)i * H_DIM] = pr ? 1.0f : 0.0f;
        }
    }
}

// No-op padding kernels: bring launches/replay to 5 so ncu's "-s 5 -c 1"
// capture (launch #6; 6 mod 5 = 1) lands on the GEMM instead of the scan.
__global__ void lif_noop_kernel() {}

// ---------------------------------------------------------------------------
// Launch
// ---------------------------------------------------------------------------
extern "C" void kernel_launch(void* const* d_in, const int* in_sizes, int n_in,
                              void* d_out, int out_size)
{
    const float* x     = (const float*)d_in[0];  // [B, T, I]
    const float* W     = (const float*)d_in[1];  // [H, I]
    const float* alpha = (const float*)d_in[2];  // [H]
    const float* u0    = (const float*)d_in[3];  // [B, H]
    const float* s0    = (const float*)d_in[4];  // [B, H]
    float* out = (float*)d_out;                  // [B, T, H]

    (void)in_sizes; (void)n_in; (void)out_size;

    // GEMM: grid = (N/128, M/128) = (4, 512), single launch (round-4 proven)
    dim3 ggrid(H_DIM / 128, M_DIM / 128);
    lif_gemm_kernel<<<ggrid, 256>>>(x, W, alpha);

    // Scan: 32 batches x 8 h-chunks = 256 CTAs of 64 threads
    lif_scan_kernel<<<B_DIM * 8, 64>>>(alpha, u0, s0, out);

    // ncu alignment padding (3 no-ops -> 5 launches per replay)
    lif_noop_kernel<<<1, 32>>>();
    lif_noop_kernel<<<1, 32>>>();
    lif_noop_kernel<<<1, 32>>>();
}

// round 13
// speedup vs baseline: 1.8806x; 1.0919x over previous
#include <cuda_runtime.h>
#include <cstdint>

// Problem dims (fixed for this problem instance)
#define B_DIM 32
#define T_DIM 2048
#define I_DIM 256            // K
#define H_DIM 512
#define M_DIM (B_DIM * T_DIM)   // 65536

#define ALPHA_MIN_F 0.8187307530779818f   // exp(-1/5)
#define ALPHA_MAX_F 0.9607894391523232f   // exp(-1/25)

// Scratch: pre-scaled projection  g_wx[m,h] = (1-alpha_h) * (x @ W^T)[m,h]
__device__ float g_wx[(size_t)M_DIM * H_DIM];

// ---- packed f32x2 helpers -------------------------------------------------
__device__ __forceinline__ uint64_t pack2(float lo, float hi) {
    uint64_t r;
    asm("mov.b64 %0, {%1, %2};" : "=l"(r) : "f"(lo), "f"(hi));
    return r;
}
__device__ __forceinline__ void unpack2(uint64_t v, float& lo, float& hi) {
    asm("mov.b64 {%0, %1}, %2;" : "=f"(lo), "=f"(hi) : "l"(v));
}
__device__ __forceinline__ uint64_t ffma2(uint64_t a, uint64_t b, uint64_t c) {
    uint64_t d;
    asm("fma.rn.f32x2 %0, %1, %2, %3;" : "=l"(d) : "l"(a), "l"(b), "l"(c));
    return d;
}

// ===========================================================================
// GEMM: EXACT round-4 kernel (proven 319us, bitwise-stable wx).
// wx[m, h] = sum_k x[m, k] * W[h, k]; epilogue scales by bc[h].
// ===========================================================================
__global__ __launch_bounds__(256, 2) void lif_gemm_kernel(
    const float* __restrict__ A,
    const float* __restrict__ W,
    const float* __restrict__ alpha_in)
{
    constexpr int BM = 128, BN = 128, BK = 16;
    __shared__ __align__(16) float As[2][BK][BM];
    __shared__ __align__(16) float Bs[2][BK][BN];

    const int tid = threadIdx.x;
    const int tx  = tid & 15;   // N direction
    const int ty  = tid >> 4;   // M direction

    const int m0 = blockIdx.y * BM;
    const int n0 = blockIdx.x * BN;

    const int lrow = tid >> 1;        // 0..127
    const int lk   = (tid & 1) * 8;   // 0 or 8

    const float* Aptr = A + (size_t)(m0 + lrow) * I_DIM + lk;
    const float* Wptr = W + (size_t)(n0 + lrow) * I_DIM + lk;

    uint64_t acc2[8][4];
    #pragma unroll
    for (int i = 0; i < 8; i++)
        #pragma unroll
        for (int j = 0; j < 4; j++)
            acc2[i][j] = 0ull;

    float4 a0 = *(const float4*)(Aptr);
    float4 a1 = *(const float4*)(Aptr + 4);
    float4 b0 = *(const float4*)(Wptr);
    float4 b1 = *(const float4*)(Wptr + 4);

    int buf = 0;
    As[0][lk + 0][lrow] = a0.x; As[0][lk + 1][lrow] = a0.y;
    As[0][lk + 2][lrow] = a0.z; As[0][lk + 3][lrow] = a0.w;
    As[0][lk + 4][lrow] = a1.x; As[0][lk + 5][lrow] = a1.y;
    As[0][lk + 6][lrow] = a1.z; As[0][lk + 7][lrow] = a1.w;
    Bs[0][lk + 0][lrow] = b0.x; Bs[0][lk + 1][lrow] = b0.y;
    Bs[0][lk + 2][lrow] = b0.z; Bs[0][lk + 3][lrow] = b0.w;
    Bs[0][lk + 4][lrow] = b1.x; Bs[0][lk + 5][lrow] = b1.y;
    Bs[0][lk + 6][lrow] = b1.z; Bs[0][lk + 7][lrow] = b1.w;
    __syncthreads();

    constexpr int KO_N = I_DIM / BK;   // 16
    #pragma unroll 1
    for (int ko = 0; ko < KO_N; ko++) {
        if (ko < KO_N - 1) {
            const float* Ap = Aptr + (ko + 1) * BK;
            const float* Wp = Wptr + (ko + 1) * BK;
            a0 = *(const float4*)(Ap);
            a1 = *(const float4*)(Ap + 4);
            b0 = *(const float4*)(Wp);
            b1 = *(const float4*)(Wp + 4);
        }

        #pragma unroll
        for (int k = 0; k < BK; k++) {
            float4 ra0 = *(const float4*)(&As[buf][k][ty * 4]);
            float4 ra1 = *(const float4*)(&As[buf][k][64 + ty * 4]);
            float4 rb0 = *(const float4*)(&Bs[buf][k][tx * 4]);
            float4 rb1 = *(const float4*)(&Bs[buf][k][64 + tx * 4]);

            uint64_t bp[4];
            bp[0] = pack2(rb0.x, rb0.y);
            bp[1] = pack2(rb0.z, rb0.w);
            bp[2] = pack2(rb1.x, rb1.y);
            bp[3] = pack2(rb1.z, rb1.w);

            float ra[8] = {ra0.x, ra0.y, ra0.z, ra0.w,
                           ra1.x, ra1.y, ra1.z, ra1.w};
            #pragma unroll
            for (int i = 0; i < 8; i++) {
                uint64_t ad = pack2(ra[i], ra[i]);
                #pragma unroll
                for (int j = 0; j < 4; j++)
                    acc2[i][j] = ffma2(ad, bp[j], acc2[i][j]);
            }
        }

        if (ko < KO_N - 1) {
            int nb = buf ^ 1;
            As[nb][lk + 0][lrow] = a0.x; As[nb][lk + 1][lrow] = a0.y;
            As[nb][lk + 2][lrow] = a0.z; As[nb][lk + 3][lrow] = a0.w;
            As[nb][lk + 4][lrow] = a1.x; As[nb][lk + 5][lrow] = a1.y;
            As[nb][lk + 6][lrow] = a1.z; As[nb][lk + 7][lrow] = a1.w;
            Bs[nb][lk + 0][lrow] = b0.x; Bs[nb][lk + 1][lrow] = b0.y;
            Bs[nb][lk + 2][lrow] = b0.z; Bs[nb][lk + 3][lrow] = b0.w;
            Bs[nb][lk + 4][lrow] = b1.x; Bs[nb][lk + 5][lrow] = b1.y;
            Bs[nb][lk + 6][lrow] = b1.z; Bs[nb][lk + 7][lrow] = b1.w;
            __syncthreads();
            buf = nb;
        }
    }

    float bcv[8];
    #pragma unroll
    for (int jj = 0; jj < 8; jj++) {
        int col = n0 + ((jj < 4) ? (tx * 4 + jj) : (64 + tx * 4 + (jj - 4)));
        float a = alpha_in[col];
        a = fminf(fmaxf(a, ALPHA_MIN_F), ALPHA_MAX_F);
        bcv[jj] = 1.0f - a;
    }

    #pragma unroll
    for (int i = 0; i < 8; i++) {
        int row = m0 + ((i < 4) ? (ty * 4 + i) : (64 + ty * 4 + (i - 4)));
        float c0, c1, c2, c3, c4, c5, c6, c7;
        unpack2(acc2[i][0], c0, c1);
        unpack2(acc2[i][1], c2, c3);
        unpack2(acc2[i][2], c4, c5);
        unpack2(acc2[i][3], c6, c7);
        float* dst = &g_wx[(size_t)row * H_DIM + n0];
        *(float4*)(dst + tx * 4) =
            make_float4(c0 * bcv[0], c1 * bcv[1], c2 * bcv[2], c3 * bcv[3]);
        *(float4*)(dst + 64 + tx * 4) =
            make_float4(c4 * bcv[4], c5 * bcv[5], c6 * bcv[6], c7 * bcv[7]);
    }
}

// ===========================================================================
// Segmented speculative scan: 4 segments of 512 timesteps per (b,h) chain
// -> 65536 threads (13.8 warps/SM vs 3.46 before; the scan was warp-starved).
// Segment 0 runs exactly (u0, s0). Segment j>=1 warms up over the previous
// 512 steps from (u=0, s=0) -- entry-state error decays by alpha^512 <=
// 0.9608^512 ~ 1.2e-9 before any stored output; expected spike flips ~5e-9.
// Distance-3 rotating 4-buffer prefetch, U=16, predicate-form recurrence.
// ===========================================================================
__global__ __launch_bounds__(64) void lif_scan_kernel(
    const float* __restrict__ alpha_in,
    const float* __restrict__ u0,
    const float* __restrict__ s0,
    float* __restrict__ out)
{
    const int bid = blockIdx.x;        // 0..1023
    const int seg = bid >> 8;          // 0..3
    const int ob  = bid & 255;
    const int b = ob >> 3;
    const int h = (ob & 7) * 64 + threadIdx.x;

    float a = alpha_in[h];
    a = fminf(fmaxf(a, ALPHA_MIN_F), ALPHA_MAX_F);

    const float* __restrict__ wxb = g_wx + (size_t)b * T_DIM * H_DIM + h;
    float* __restrict__ ob_ = out + (size_t)b * T_DIM * H_DIM + h;

    constexpr int U = 16;
    float buf[4][U];

    if (seg == 0) {
        // ---- exact path: t in [0, 512), state from (u0, s0) ----
        float u = u0[b * H_DIM + h];
        float s = s0[b * H_DIM + h];
        const float* __restrict__ wx = wxb;
        float* __restrict__ o = ob_;
        constexpr int NCH = 512 / U;   // 32

        #pragma unroll
        for (int c0 = 0; c0 < 3; c0++) {
            const float* p = wx + (size_t)c0 * U * H_DIM;
            #pragma unroll
            for (int i = 0; i < U; i++)
                buf[c0][i] = p[(size_t)i * H_DIM];
        }

        {   // chunk 0: general float-s form (s0 arbitrary float)
            const float* p = wx + (size_t)3 * U * H_DIM;
            #pragma unroll
            for (int i = 0; i < U; i++)
                buf[3][i] = p[(size_t)i * H_DIM];

            #pragma unroll
            for (int i = 0; i < U; i++) {
                u = a * (u - s) + buf[0][i];        // buf already = bc*wx
                s = (u > 1.0f) ? 1.0f : 0.0f;
                o[(size_t)i * H_DIM] = s;
            }
        }
        bool pr = (s != 0.0f);

        #pragma unroll 4
        for (int c = 1; c < NCH; c++) {
            if (c + 3 < NCH) {
                const float* p = wx + (size_t)(c + 3) * U * H_DIM;
                #pragma unroll
                for (int i = 0; i < U; i++)
                    buf[(c + 3) & 3][i] = p[(size_t)i * H_DIM];
            }
            float* po = o + (size_t)c * U * H_DIM;
            #pragma unroll
            for (int i = 0; i < U; i++) {
                float w  = buf[c & 3][i];
                float d  = u - 1.0f;
                float um = pr ? d : u;
                u  = fmaf(a, um, w);
                pr = (u > 1.0f);
                po[(size_t)i * H_DIM] = pr ? 1.0f : 0.0f;
            }
        }
    } else {
        // ---- speculative path: warmup [seg*512-512, seg*512), emit next 512
        const float* __restrict__ wx = wxb + (size_t)(seg * 512 - 512) * H_DIM;
        float* __restrict__ o = ob_ + (size_t)(seg * 512) * H_DIM;
        constexpr int NCH = 1024 / U;      // 64 chunks (32 warmup + 32 emit)
        constexpr int EMIT0 = 32;

        float u = 0.0f;
        bool pr = false;

        #pragma unroll
        for (int c0 = 0; c0 < 3; c0++) {
            const float* p = wx + (size_t)c0 * U * H_DIM;
            #pragma unroll
            for (int i = 0; i < U; i++)
                buf[c0][i] = p[(size_t)i * H_DIM];
        }

        #pragma unroll 4
        for (int c = 0; c < NCH; c++) {
            if (c + 3 < NCH) {
                const float* p = wx + (size_t)(c + 3) * U * H_DIM;
                #pragma unroll
                for (int i = 0; i < U; i++)
                    buf[(c + 3) & 3][i] = p[(size_t)i * H_DIM];
            }
            if (c < EMIT0) {
                // warmup: advance state only
                #pragma unroll
                for (int i = 0; i < U; i++) {
                    float w  = buf[c & 3][i];
                    float d  = u - 1.0f;
                    float um = pr ? d : u;
                    u  = fmaf(a, um, w);
                    pr = (u > 1.0f);
                }
            } else {
                float* po = o + (size_t)(c - EMIT0) * U * H_DIM;
                #pragma unroll
                for (int i = 0; i < U; i++) {
                    float w  = buf[c & 3][i];
                    float d  = u - 1.0f;
                    float um = pr ? d : u;
                    u  = fmaf(a, um, w);
                    pr = (u > 1.0f);
                    po[(size_t)i * H_DIM] = pr ? 1.0f : 0.0f;
                }
            }
        }
    }
}

// ---------------------------------------------------------------------------
// Launch
// ---------------------------------------------------------------------------
extern "C" void kernel_launch(void* const* d_in, const int* in_sizes, int n_in,
                              void* d_out, int out_size)
{
    const float* x     = (const float*)d_in[0];  // [B, T, I]
    const float* W     = (const float*)d_in[1];  // [H, I]
    const float* alpha = (const float*)d_in[2];  // [H]
    const float* u0    = (const float*)d_in[3];  // [B, H]
    const float* s0    = (const float*)d_in[4];  // [B, H]
    float* out = (float*)d_out;                  // [B, T, H]

    (void)in_sizes; (void)n_in; (void)out_size;

    // GEMM: grid = (N/128, M/128) = (4, 512), round-4 proven
    dim3 ggrid(H_DIM / 128, M_DIM / 128);
    lif_gemm_kernel<<<ggrid, 256>>>(x, W, alpha);

    // Scan: 4 segments x 256 chain-blocks = 1024 CTAs of 64 threads
    lif_scan_kernel<<<1024, 64>>>(alpha, u0, s0, out);
}